// round 2
// baseline (speedup 1.0000x reference)
#include <cuda_runtime.h>
#include <math.h>

// Problem constants (fixed by reference)
#define BB   4
#define NN   4096
#define DD   1024
#define HH   16
#define DKC  64
#define MMC  256
#define BN   16384          // B*N
#define BHC  64             // B*H
#define QKVLD 3072          // 3*D

// -------- scratch (device globals; no allocation allowed) --------
__device__ float g_qkv [(size_t)BN * QKVLD];      // 192 MB: [b*N+n][3D]
__device__ float g_Qf  [(size_t)BHC * NN * MMC];  // 256 MB: [(b*H+h)*N+n][M]
__device__ float g_Kf  [(size_t)BHC * NN * MMC];  // 256 MB
__device__ float g_S   [BHC * MMC * DKC];         // 4 MB:  [(bh*M+m)*dk+d]
__device__ float g_Ksum[BHC * MMC];
__device__ float g_ctx [(size_t)BN * DD];         // 64 MB: [b*N+n][D] (h*64+d)
__device__ float g_valid[BN];
__device__ int   g_maskmode;                      // 0=int32, 1=uint8/bool, 2=float32

// -------- mask dtype detection (scan first 16KB, safe under all layouts) ----
__global__ void detect_mask_kernel(const unsigned int* __restrict__ m)
{
    __shared__ int sa, sb;
    if (threadIdx.x == 0) { sa = 0; sb = 0; }
    __syncthreads();
    int a = 0, b = 0;
    for (int i = threadIdx.x; i < 4096; i += blockDim.x) {
        unsigned v = m[i];
        if (v == 0x3F800000u) b = 1;
        else if (v > 1u) a = 1;
    }
    if (a) atomicOr(&sa, 1);
    if (b) atomicOr(&sb, 1);
    __syncthreads();
    if (threadIdx.x == 0) g_maskmode = sa ? 1 : (sb ? 2 : 0);
}

__global__ void build_valid_kernel(const void* __restrict__ mask)
{
    int i = blockIdx.x * blockDim.x + threadIdx.x;
    if (i >= BN) return;
    int mode = g_maskmode;
    int pad;
    if (mode == 1)      pad = ((const unsigned char*)mask)[i] != 0;
    else if (mode == 2) pad = ((const float*)mask)[i] != 0.0f;
    else                pad = ((const int*)mask)[i] != 0;
    g_valid[i] = pad ? 0.0f : 1.0f;
}

// -------- generic NT GEMM: C[i][j] = sum_k A[i][k]*B[j][k] + bias[j] --------
// A: IxK row-major, B: JxK row-major. I,J multiples of 128; K multiple of 16.
// useGlobalA: A = g_ctx (ignore Aparam). useGlobalC: C = g_qkv (ignore Cparam).
__global__ __launch_bounds__(256)
void gemm_nt_kernel(const float* __restrict__ Aparam,
                    const float* __restrict__ Bm,
                    const float* __restrict__ bias,
                    float* __restrict__ Cparam,
                    int I, int J, int K, int useGlobalA, int useGlobalC)
{
    const float* A = useGlobalA ? (const float*)g_ctx : Aparam;
    float*       C = useGlobalC ? (float*)g_qkv : Cparam;

    __shared__ float As[16][132];
    __shared__ float Bs[16][132];
    int tid = threadIdx.x;
    int i0 = blockIdx.y * 128, j0 = blockIdx.x * 128;
    int tx = tid & 15, ty = tid >> 4;

    float acc[8][8];
#pragma unroll
    for (int r = 0; r < 8; r++)
#pragma unroll
        for (int c = 0; c < 8; c++) acc[r][c] = 0.0f;

    for (int k0 = 0; k0 < K; k0 += 16) {
#pragma unroll
        for (int l = 0; l < 2; l++) {
            int f = tid + l * 256;
            int row = f >> 2, kq = (f & 3) * 4;
            float4 va = *(const float4*)(A + (size_t)(i0 + row) * K + k0 + kq);
            As[kq + 0][row] = va.x; As[kq + 1][row] = va.y;
            As[kq + 2][row] = va.z; As[kq + 3][row] = va.w;
            float4 vb = *(const float4*)(Bm + (size_t)(j0 + row) * K + k0 + kq);
            Bs[kq + 0][row] = vb.x; Bs[kq + 1][row] = vb.y;
            Bs[kq + 2][row] = vb.z; Bs[kq + 3][row] = vb.w;
        }
        __syncthreads();
#pragma unroll
        for (int kk = 0; kk < 16; kk++) {
            float a[8], bb[8];
            *(float4*)&a[0]  = *(const float4*)&As[kk][ty * 8];
            *(float4*)&a[4]  = *(const float4*)&As[kk][ty * 8 + 4];
            *(float4*)&bb[0] = *(const float4*)&Bs[kk][tx * 8];
            *(float4*)&bb[4] = *(const float4*)&Bs[kk][tx * 8 + 4];
#pragma unroll
            for (int r = 0; r < 8; r++)
#pragma unroll
                for (int c = 0; c < 8; c++)
                    acc[r][c] = fmaf(a[r], bb[c], acc[r][c]);
        }
        __syncthreads();
    }

    float4 b0 = *(const float4*)&bias[j0 + tx * 8];
    float4 b1 = *(const float4*)&bias[j0 + tx * 8 + 4];
#pragma unroll
    for (int r = 0; r < 8; r++) {
        size_t off = (size_t)(i0 + ty * 8 + r) * J + j0 + tx * 8;
        float4 o0 = make_float4(acc[r][0] + b0.x, acc[r][1] + b0.y,
                                acc[r][2] + b0.z, acc[r][3] + b0.w);
        float4 o1 = make_float4(acc[r][4] + b1.x, acc[r][5] + b1.y,
                                acc[r][6] + b1.z, acc[r][7] + b1.w);
        *(float4*)(C + off)     = o0;
        *(float4*)(C + off + 4) = o1;
    }
}

// -------- phi kernel: per (b,h), 32-row tile; computes exp features ---------
// Reads g_qkv at column offset qoff (0 for Q, DD for K).
// isQ=1: pre-mask input, write g_Qf. isQ=0: post-mask output, write g_Kf.
__global__ __launch_bounds__(256)
void phi_kernel(const float* __restrict__ omega, int qoff, int isQ)
{
    __shared__ float omT[MMC * 33];  // [m][kk] padded, per 32-k chunk
    __shared__ float tS[32 * 64];
    __shared__ float sqS[32];
    __shared__ float vS[32];

    int tid = threadIdx.x;
    int w = tid >> 5, lane = tid & 31;
    int bh = blockIdx.y;
    int b = bh / HH, h = bh % HH;
    int n0 = blockIdx.x * 32;

    float* F = isQ ? (float*)g_Qf : (float*)g_Kf;
    const float* Tbase = (const float*)g_qkv + qoff;

    // load t tile (32 x 64), apply preMask, compute 0.5*|t|^2 via shfl
    {
        int r = tid >> 3;
        int ks = (tid & 7) * 8;
        size_t rowoff = ((size_t)(b * NN + n0 + r)) * QKVLD + h * DKC;
        float vl = g_valid[b * NN + n0 + r];
        float4 a = *(const float4*)(Tbase + rowoff + ks);
        float4 c = *(const float4*)(Tbase + rowoff + ks + 4);
        if (isQ) {
            a.x *= vl; a.y *= vl; a.z *= vl; a.w *= vl;
            c.x *= vl; c.y *= vl; c.z *= vl; c.w *= vl;
        }
        *(float4*)&tS[r * 64 + ks]     = a;
        *(float4*)&tS[r * 64 + ks + 4] = c;
        float p = a.x*a.x + a.y*a.y + a.z*a.z + a.w*a.w
                + c.x*c.x + c.y*c.y + c.z*c.z + c.w*c.w;
        p += __shfl_xor_sync(0xffffffffu, p, 1);
        p += __shfl_xor_sync(0xffffffffu, p, 2);
        p += __shfl_xor_sync(0xffffffffu, p, 4);
        if ((tid & 7) == 0) { sqS[r] = 0.5f * p; vS[r] = vl; }
    }

    float acc[4][8];
#pragma unroll
    for (int i = 0; i < 4; i++)
#pragma unroll
        for (int j = 0; j < 8; j++) acc[i][j] = 0.0f;

    for (int kc = 0; kc < DKC; kc += 32) {
        if (kc) __syncthreads();
        // each warp loads 32 m-rows, coalesced 32-float reads, conflict-free writes
#pragma unroll
        for (int i = 0; i < 32; i++) {
            int m = w * 32 + i;
            omT[m * 33 + lane] = omega[((size_t)(h * MMC + m)) * DKC + kc + lane];
        }
        __syncthreads();
#pragma unroll
        for (int kk = 0; kk < 32; kk++) {
            float tv[4];
#pragma unroll
            for (int i = 0; i < 4; i++) tv[i] = tS[(w * 4 + i) * 64 + kc + kk];
#pragma unroll
            for (int j = 0; j < 8; j++) {
                float ov = omT[(lane + j * 32) * 33 + kk];  // strided-m: bank-clean
#pragma unroll
                for (int i = 0; i < 4; i++)
                    acc[i][j] = fmaf(tv[i], ov, acc[i][j]);
            }
        }
    }

    // row-max over all 256 m (8 per-thread + warp reduce), exp epilogue
#pragma unroll
    for (int i = 0; i < 4; i++) {
        float rm = acc[i][0];
#pragma unroll
        for (int j = 1; j < 8; j++) rm = fmaxf(rm, acc[i][j]);
        rm = fmaxf(rm, __shfl_xor_sync(0xffffffffu, rm, 16));
        rm = fmaxf(rm, __shfl_xor_sync(0xffffffffu, rm, 8));
        rm = fmaxf(rm, __shfl_xor_sync(0xffffffffu, rm, 4));
        rm = fmaxf(rm, __shfl_xor_sync(0xffffffffu, rm, 2));
        rm = fmaxf(rm, __shfl_xor_sync(0xffffffffu, rm, 1));
        int r = w * 4 + i;
        float sq = sqS[r];
        float vp = isQ ? 1.0f : vS[r];
        size_t base = ((size_t)bh * NN + n0 + r) * MMC;
#pragma unroll
        for (int j = 0; j < 8; j++)
            F[base + lane + j * 32] = expf(acc[i][j] - rm - sq) * 0.0625f * vp;
    }
}

// -------- S kernel: S[m][d] = sum_n Kf[n][m]*V[n][d]; Ksum[m]=sum_n Kf[n][m] -
__global__ __launch_bounds__(256)
void s_kernel()
{
    __shared__ float Ks[32][68];
    __shared__ float Vs[32][68];
    int tid = threadIdx.x;
    int bh = blockIdx.y;
    int m0 = blockIdx.x * 64;
    int b = bh / HH, h = bh % HH;
    int dt = tid & 15, mt = tid >> 4;

    const float* Vbase = (const float*)g_qkv + 2 * DD;

    float acc[4][4];
#pragma unroll
    for (int i = 0; i < 4; i++)
#pragma unroll
        for (int j = 0; j < 4; j++) acc[i][j] = 0.0f;
    float ks[4] = {0.f, 0.f, 0.f, 0.f};

    size_t kfbase = ((size_t)bh * NN) * MMC + m0;

    for (int n0 = 0; n0 < NN; n0 += 32) {
        int r = tid >> 3, c = (tid & 7) * 8;
        {
            float4 a = *(const float4*)&g_Kf[kfbase + (size_t)(n0 + r) * MMC + c];
            float4 d = *(const float4*)&g_Kf[kfbase + (size_t)(n0 + r) * MMC + c + 4];
            *(float4*)&Ks[r][c]     = a;
            *(float4*)&Ks[r][c + 4] = d;
            size_t voff = ((size_t)(b * NN + n0 + r)) * QKVLD + h * DKC;
            float4 va = *(const float4*)(Vbase + voff + c);
            float4 vd = *(const float4*)(Vbase + voff + c + 4);
            *(float4*)&Vs[r][c]     = va;
            *(float4*)&Vs[r][c + 4] = vd;
        }
        __syncthreads();
#pragma unroll
        for (int nn = 0; nn < 32; nn++) {
            float4 kf = *(const float4*)&Ks[nn][mt * 4];
            float4 vv = *(const float4*)&Vs[nn][dt * 4];
            float kfa[4] = {kf.x, kf.y, kf.z, kf.w};
            float vva[4] = {vv.x, vv.y, vv.z, vv.w};
#pragma unroll
            for (int i = 0; i < 4; i++) {
                ks[i] += kfa[i];
#pragma unroll
                for (int j = 0; j < 4; j++)
                    acc[i][j] = fmaf(kfa[i], vva[j], acc[i][j]);
            }
        }
        __syncthreads();
    }
#pragma unroll
    for (int i = 0; i < 4; i++) {
        int m = m0 + mt * 4 + i;
        *(float4*)&g_S[((size_t)bh * MMC + m) * DKC + dt * 4] =
            make_float4(acc[i][0], acc[i][1], acc[i][2], acc[i][3]);
        if (dt == 0) g_Ksum[bh * MMC + m] = ks[i];
    }
}

// -------- ctx kernel: ctx[n][d] = (Qf@S)/(Qf.Ksum+eps)*valid, into (B,N,D) ---
__global__ __launch_bounds__(256)
void ctx_kernel()
{
    __shared__ float Ssh[64][68];
    __shared__ float Qs[64][68];
    __shared__ float KsumS[64];
    __shared__ float denomS[64];
    __shared__ float vSh[64];

    int tid = threadIdx.x;
    int bh = blockIdx.y;
    int n0 = blockIdx.x * 64;
    int b = bh / HH, h = bh % HH;
    int dt = tid & 15, rt = tid >> 4;

    if (tid < 64) vSh[tid] = g_valid[b * NN + n0 + tid];

    float acc[4][4];
#pragma unroll
    for (int i = 0; i < 4; i++)
#pragma unroll
        for (int j = 0; j < 4; j++) acc[i][j] = 0.0f;
    float dacc[4] = {0.f, 0.f, 0.f, 0.f};

    for (int mc = 0; mc < MMC; mc += 64) {
        __syncthreads();   // protects smem reuse; first iter orders vSh too
#pragma unroll
        for (int l = 0; l < 4; l++) {
            int f = tid + l * 256;
            int mr = f >> 4, c = (f & 15) * 4;
            float4 sv = *(const float4*)&g_S[((size_t)bh * MMC + mc + mr) * DKC + c];
            *(float4*)&Ssh[mr][c] = sv;
            float4 qv = *(const float4*)&g_Qf[((size_t)bh * NN + n0 + mr) * MMC + mc + c];
            *(float4*)&Qs[mr][c] = qv;
        }
        if (tid < 64) KsumS[tid] = g_Ksum[bh * MMC + mc + tid];
        __syncthreads();
#pragma unroll 8
        for (int mm = 0; mm < 64; mm++) {
            float q[4];
#pragma unroll
            for (int i = 0; i < 4; i++) q[i] = Qs[rt * 4 + i][mm];
            float4 s4 = *(const float4*)&Ssh[mm][dt * 4];
            float km = KsumS[mm];
#pragma unroll
            for (int i = 0; i < 4; i++) {
                dacc[i] = fmaf(q[i], km, dacc[i]);
                acc[i][0] = fmaf(q[i], s4.x, acc[i][0]);
                acc[i][1] = fmaf(q[i], s4.y, acc[i][1]);
                acc[i][2] = fmaf(q[i], s4.z, acc[i][2]);
                acc[i][3] = fmaf(q[i], s4.w, acc[i][3]);
            }
        }
    }
    if (dt == 0) {
#pragma unroll
        for (int i = 0; i < 4; i++) denomS[rt * 4 + i] = dacc[i] + 1e-6f;
    }
    __syncthreads();
#pragma unroll
    for (int i = 0; i < 4; i++) {
        int r = rt * 4 + i;
        float inv = 1.0f / denomS[r];
        float vl = vSh[r];
        size_t off = ((size_t)(b * NN + n0 + r)) * DD + h * DKC + dt * 4;
        *(float4*)&g_ctx[off] = make_float4(acc[i][0] * inv * vl,
                                            acc[i][1] * inv * vl,
                                            acc[i][2] * inv * vl,
                                            acc[i][3] * inv * vl);
    }
}

// ---------------------------------------------------------------------------
// kernel_launch contains ONLY kernel launches — no runtime API calls at all,
// so it is trivially graph-capturable.
extern "C" void kernel_launch(void* const* d_in, const int* in_sizes, int n_in,
                              void* d_out, int out_size)
{
    const float* x     = (const float*)d_in[0];
    const float* Wqkv  = (const float*)d_in[1];
    const float* bqkv  = (const float*)d_in[2];
    const float* Wout  = (const float*)d_in[3];
    const float* bout  = (const float*)d_in[4];
    const float* omega = (const float*)d_in[5];
    const void*  mask  = d_in[6];
    float* out = (float*)d_out;

    detect_mask_kernel<<<1, 256>>>((const unsigned int*)mask);
    build_valid_kernel<<<BN / 256, 256>>>(mask);

    // QKV projection: g_qkv = x @ Wqkv^T + bqkv   (C -> g_qkv via flag)
    gemm_nt_kernel<<<dim3(QKVLD / 128, BN / 128), 256>>>(
        x, Wqkv, bqkv, nullptr, BN, QKVLD, DD, /*useGlobalA=*/0, /*useGlobalC=*/1);

    // phi(Q) (pre-masked) -> g_Qf, phi(K) (post-masked) -> g_Kf
    dim3 gp(NN / 32, BHC);
    phi_kernel<<<gp, 256>>>(omega, /*qoff=*/0,  /*isQ=*/1);
    phi_kernel<<<gp, 256>>>(omega, /*qoff=*/DD, /*isQ=*/0);

    // S and Ksum from g_Kf and V slab of g_qkv
    s_kernel<<<dim3(MMC / 64, BHC), 256>>>();

    // ctx = (Qf @ S) / (Qf . Ksum + eps) * valid  -> g_ctx (B,N,D)
    ctx_kernel<<<dim3(NN / 64, BHC), 256>>>();

    // out = g_ctx @ Wout^T + bout   (A -> g_ctx via flag)
    gemm_nt_kernel<<<dim3(DD / 128, BN / 128), 256>>>(
        nullptr, Wout, bout, out, BN, DD, DD, /*useGlobalA=*/1, /*useGlobalC=*/0);
}